// round 14
// baseline (speedup 1.0000x reference)
#include <cuda_runtime.h>
#include <math.h>

#define NK   16
#define DLAT 128
#define MM   100
#define MP   104            // MM padded to multiple of 8 (zero coeffs)
#define NS   136
#define NB   8192
#define ROWS 32
#define THREADS 512
#define NSLOT 32            // half-warp state slots per CTA
#define ZSTRIDE 132

typedef unsigned long long ull;

#define FMA2(d, a, b, c) \
    asm("fma.rn.f32x2 %0, %1, %2, %3;" : "=l"(d) : "l"(a), "l"(b), "l"(c))
#define PACK2(d, x) \
    asm("mov.b64 %0, {%1, %1};" : "=l"(d) : "f"(x))
#define UNPACK2(lo, hi, v) \
    asm("mov.b64 {%0, %1}, %2;" : "=f"(lo), "=f"(hi) : "l"(v))

// ---------- device scratch ----------
__device__ float g_logpi[NS];
__device__ float g_bb[NS];        // |muB|^2
__device__ float g_cb[NS];        // muB . (muA - muB)
__device__ float g_u[NS * MP];    // exp(gamma_s * w_m^2), zero-padded

// ---------- prep ----------
__global__ void k_prep(const float* __restrict__ pi, const float* __restrict__ mu,
                       const int* __restrict__ A, const int* __restrict__ B,
                       const float* __restrict__ w, float* out_pi, float* out_mu) {
    int tid = threadIdx.x;
    if (blockIdx.x == 0) {
        __shared__ float red[256];
        float v = (tid < NS) ? pi[tid] : -INFINITY;
        red[tid] = v; __syncthreads();
        for (int off = 128; off >= 1; off >>= 1) {
            if (tid < off) red[tid] = fmaxf(red[tid], red[tid + off]);
            __syncthreads();
        }
        float mx = red[0]; __syncthreads();
        float e = (tid < NS) ? expf(v - mx) : 0.0f;
        red[tid] = e; __syncthreads();
        for (int off = 128; off >= 1; off >>= 1) {
            if (tid < off) red[tid] += red[tid + off];
            __syncthreads();
        }
        float ssum = red[0];
        if (tid < NS) {
            float ps = e / ssum;
            if (out_pi) out_pi[tid] = ps;
            g_logpi[tid] = logf(ps + 1e-30f);
        }
        if (out_mu) {
            for (int i = tid; i < DLAT * NK; i += blockDim.x) out_mu[i] = mu[i];
        }
    } else {
        int s = blockIdx.x - 1;
        __shared__ float r0[256], r1[256], r2[256];
        __shared__ float gam_sh;
        int ia = A[s], ib = B[s];
        float vb = 0.0f, dv = 0.0f;
        if (tid < DLAT) {
            float va = mu[tid * NK + ia];
            vb = mu[tid * NK + ib];
            dv = va - vb;
        }
        r0[tid] = vb * vb; r1[tid] = vb * dv; r2[tid] = dv * dv;
        __syncthreads();
        for (int off = 128; off >= 1; off >>= 1) {
            if (tid < off) {
                r0[tid] += r0[tid + off];
                r1[tid] += r1[tid + off];
                r2[tid] += r2[tid + off];
            }
            __syncthreads();
        }
        if (tid == 0) {
            g_bb[s] = r0[0];
            g_cb[s] = r1[0];
            gam_sh = -0.5f * r2[0];
        }
        __syncthreads();
        if (tid < MP) {
            float uval = 0.0f;
            if (tid < MM) {
                float wv = w[tid];
                uval = expf(gam_sh * wv * wv);
            }
            g_u[s * MP + tid] = uval;
        }
    }
}

// ---------- main ----------
__global__ void __launch_bounds__(THREADS, 2)
k_main(const float* __restrict__ z, const float* __restrict__ mu,
       const int* __restrict__ A, const int* __restrict__ B,
       const float* __restrict__ w, float* __restrict__ out_lp) {
    extern __shared__ float sm[];
    float* su    = sm;                        // NS*MP = 14144
    float* zs    = su + NS * MP;              // 32*132 = 4224
    float* msps  = zs + ROWS * ZSTRIDE;       // 2048 (mu for GEMM; psum after)
    float* sG    = msps + 2048;               // 32*17 = 544
    float* sz2   = sG + ROWS * 17;            // 32
    float* zpart = sz2 + ROWS;                // 32*16 = 512
    float* sPf   = zpart + ROWS * 16;         // NS*4 = 544

    int tid = threadIdx.x;
    int b0 = blockIdx.x * ROWS;

    // async copy of u-table (overlaps staging + GEMM)
    {
        const float4* gu4 = (const float4*)g_u;
        for (int i = tid; i < NS * MP / 4; i += THREADS) {
            unsigned int dst = (unsigned int)__cvta_generic_to_shared(su + 4 * i);
            asm volatile("cp.async.cg.shared.global [%0], [%1], 16;"
                         :: "r"(dst), "l"(gu4 + i));
        }
        asm volatile("cp.async.commit_group;");
    }

    // stage z tile + per-row partial sq-sums (16 threads per row, 2 float4 each)
    {
        int rrow = tid >> 4;                 // 0..31
        int c16  = tid & 15;
        const float4* zrow = (const float4*)(z + (size_t)(b0 + rrow) * DLAT);
        float* zd = zs + rrow * ZSTRIDE;
        float zz = 0.0f;
#pragma unroll
        for (int jj = 0; jj < 2; jj++) {
            int c4 = c16 + 16 * jj;
            float4 v = zrow[c4];
            float* dst = zd + c4 * 4;
            dst[0] = v.x; dst[1] = v.y; dst[2] = v.z; dst[3] = v.w;
            zz = fmaf(v.x, v.x, zz);
            zz = fmaf(v.y, v.y, zz);
            zz = fmaf(v.z, v.z, zz);
            zz = fmaf(v.w, v.w, zz);
        }
        zpart[rrow * 16 + c16] = zz;
    }
    for (int i = tid; i < DLAT * NK; i += THREADS) msps[i] = mu[i];
    if (tid < NS) {
        sPf[4 * tid + 0] = g_logpi[tid] - 0.5f * g_bb[tid];
        sPf[4 * tid + 1] = g_cb[tid];
        sPf[4 * tid + 2] = __int_as_float(A[tid]);
        sPf[4 * tid + 3] = __int_as_float(B[tid]);
    }
    __syncthreads();

    // z2 finalize
    if (tid < ROWS) {
        const float* zp = zpart + tid * 16;
        float t = 0.0f;
#pragma unroll
        for (int q = 0; q < 16; q++) t += zp[q];
        sz2[tid] = t;
    }

    // fused GEMM: one (row, k) per thread
    {
        int k = tid & 15, r = tid >> 4;      // r in 0..31
        const float* zr = zs + r * ZSTRIDE;
        float acc = 0.0f;
#pragma unroll 8
        for (int d4 = 0; d4 < DLAT / 4; d4++) {
            float4 zv = *(const float4*)(zr + 4 * d4);
            int db = d4 * 4;
            acc = fmaf(zv.x, msps[(db + 0) * NK + k], acc);
            acc = fmaf(zv.y, msps[(db + 1) * NK + k], acc);
            acc = fmaf(zv.z, msps[(db + 2) * NK + k], acc);
            acc = fmaf(zv.w, msps[(db + 3) * NK + k], acc);
        }
        sG[r * 17 + k] = acc;
    }
    asm volatile("cp.async.wait_group 0;");
    __syncthreads();   // fences GEMM results, u-table, msps->psum reuse

    // main loop: half-warp = state slot; lane owns rows r0i and r0i+16
    int lane = tid & 31;
    int warp = tid >> 5;                     // 0..15
    int r0i = lane & 15;
    int slot = warp * 2 + (lane >> 4);       // 0..31
    int cnt = (slot < 8) ? 5 : 4;            // 8*5 + 24*4 = 136
    float w1 = w[1];
    const float* gra = sG + r0i * 17;
    const float* grb = sG + (r0i + 16) * 17;
    const float4* sP4 = (const float4*)sPf;
    float acc_a = 0.0f, acc_b = 0.0f;

    int s = slot;
#pragma unroll 1
    for (int i = 0; i < cnt; i++) {
        float4 P = sP4[s];
        int ia = __float_as_int(P.z), ib = __float_as_int(P.w);
        float gAa = gra[ia], gBa = gra[ib];
        float gAb = grb[ia], gBb = grb[ib];

        float r1a = __expf((gAa - gBa - P.y) * w1);
        float r1b = __expf((gAb - gBb - P.y) * w1);
        float ea = __expf(P.x + gBa);
        float eb = __expf(P.x + gBb);
        float r4a = (r1a * r1a) * (r1a * r1a);
        float r4b = (r1b * r1b) * (r1b * r1b);
        ull r4ap, r4bp;
        PACK2(r4ap, r4a); PACK2(r4bp, r4b);
        const ulonglong2* up = (const ulonglong2*)(su + s * MP);

        // software-pipelined Horner: load uu[g-1] before consuming uu[g]
        ull Fa01 = 0ull, Fa23 = 0ull, Fb01 = 0ull, Fb23 = 0ull;
        ulonglong2 uu = up[MP / 4 - 1];
#pragma unroll
        for (int g = MP / 4 - 1; g >= 0; g--) {
            ulonglong2 un;
            if (g > 0) un = up[g - 1];
            FMA2(Fa01, r4ap, Fa01, uu.x);
            FMA2(Fa23, r4ap, Fa23, uu.y);
            FMA2(Fb01, r4bp, Fb01, uu.x);
            FMA2(Fb23, r4bp, Fb23, uu.y);
            if (g > 0) uu = un;
        }

        // epilogue: V = F01 + r2*F23 ; f = V.lo + r1*V.hi
        ull V; float X, Y; ull r2p;
        PACK2(r2p, r1a * r1a);
        FMA2(V, r2p, Fa23, Fa01); UNPACK2(X, Y, V);
        acc_a = fmaf(ea, fmaf(r1a, Y, X), acc_a);
        PACK2(r2p, r1b * r1b);
        FMA2(V, r2p, Fb23, Fb01); UNPACK2(X, Y, V);
        acc_b = fmaf(eb, fmaf(r1b, Y, X), acc_b);

        s += NSLOT;
    }

    float* psum = msps;                      // reuse as [NSLOT][ROWS]
    psum[slot * ROWS + r0i]      = acc_a;
    psum[slot * ROWS + r0i + 16] = acc_b;
    __syncthreads();
    if (tid < ROWS) {
        float tot = 0.0f;
#pragma unroll
        for (int q = 0; q < NSLOT; q++) tot += psum[q * ROWS + tid];
        const float C = -0.5f * (float)DLAT * 1.8378770664093453f;  // -D/2 ln(2pi)
        out_lp[b0 + tid] = C - 0.5f * sz2[tid] - logf((float)MM) + logf(tot);
    }
}

// ---------- launcher ----------
extern "C" void kernel_launch(void* const* d_in, const int* in_sizes, int n_in,
                              void* d_out, int out_size) {
    const float* z  = (const float*)d_in[0];
    const float* mu = (const float*)d_in[1];
    const float* pi = (const float*)d_in[2];
    const float* w  = (const float*)d_in[3];
    const int*   A  = (const int*)d_in[4];
    const int*   B  = (const int*)d_in[5];
    float* out = (float*)d_out;

    float* out_pi = nullptr;
    float* out_mu = nullptr;
    float* out_lp = out;
    if (out_size >= NS + DLAT * NK + NB) {
        out_pi = out;
        out_mu = out + NS;
        out_lp = out + NS + DLAT * NK;
    }

    const int SMEM = (NS * MP + ROWS * ZSTRIDE + 2048 + ROWS * 17 + ROWS
                      + ROWS * 16 + NS * 4) * 4;
    cudaFuncSetAttribute(k_main, cudaFuncAttributeMaxDynamicSharedMemorySize, SMEM);

    k_prep<<<1 + NS, 256>>>(pi, mu, A, B, w, out_pi, out_mu);
    k_main<<<NB / ROWS, THREADS, SMEM>>>(z, mu, A, B, w, out_lp);
}

// round 15
// speedup vs baseline: 1.1476x; 1.1476x over previous
#include <cuda_runtime.h>
#include <math.h>

#define NK   16
#define DLAT 128
#define MM   100
#define MP   104            // MM padded to multiple of 8 (zero coeffs)
#define NS   136
#define NB   8192
#define ROWS 64
#define THREADS 512
#define NSLOT 32            // half-warp state slots per CTA
#define ZSTRIDE 132

typedef unsigned long long ull;

#define FMA2(d, a, b, c) \
    asm("fma.rn.f32x2 %0, %1, %2, %3;" : "=l"(d) : "l"(a), "l"(b), "l"(c))
#define PACK2(d, x) \
    asm("mov.b64 %0, {%1, %1};" : "=l"(d) : "f"(x))
#define UNPACK2(lo, hi, v) \
    asm("mov.b64 {%0, %1}, %2;" : "=f"(lo), "=f"(hi) : "l"(v))

// ---------- device scratch ----------
__device__ float g_logpi[NS];
__device__ float g_bb[NS];        // |muB|^2
__device__ float g_cb[NS];        // muB . (muA - muB)
__device__ float g_u[NS * MP];    // exp(gamma_s * w_m^2), zero-padded

// ---------- prep ----------
__global__ void k_prep(const float* __restrict__ pi, const float* __restrict__ mu,
                       const int* __restrict__ A, const int* __restrict__ B,
                       const float* __restrict__ w, float* out_pi, float* out_mu) {
    int tid = threadIdx.x;
    if (blockIdx.x == 0) {
        __shared__ float red[256];
        float v = (tid < NS) ? pi[tid] : -INFINITY;
        red[tid] = v; __syncthreads();
        for (int off = 128; off >= 1; off >>= 1) {
            if (tid < off) red[tid] = fmaxf(red[tid], red[tid + off]);
            __syncthreads();
        }
        float mx = red[0]; __syncthreads();
        float e = (tid < NS) ? expf(v - mx) : 0.0f;
        red[tid] = e; __syncthreads();
        for (int off = 128; off >= 1; off >>= 1) {
            if (tid < off) red[tid] += red[tid + off];
            __syncthreads();
        }
        float ssum = red[0];
        if (tid < NS) {
            float ps = e / ssum;
            if (out_pi) out_pi[tid] = ps;
            g_logpi[tid] = logf(ps + 1e-30f);
        }
        if (out_mu) {
            for (int i = tid; i < DLAT * NK; i += blockDim.x) out_mu[i] = mu[i];
        }
    } else {
        int s = blockIdx.x - 1;
        __shared__ float r0[256], r1[256], r2[256];
        __shared__ float gam_sh;
        int ia = A[s], ib = B[s];
        float vb = 0.0f, dv = 0.0f;
        if (tid < DLAT) {
            float va = mu[tid * NK + ia];
            vb = mu[tid * NK + ib];
            dv = va - vb;
        }
        r0[tid] = vb * vb; r1[tid] = vb * dv; r2[tid] = dv * dv;
        __syncthreads();
        for (int off = 128; off >= 1; off >>= 1) {
            if (tid < off) {
                r0[tid] += r0[tid + off];
                r1[tid] += r1[tid + off];
                r2[tid] += r2[tid + off];
            }
            __syncthreads();
        }
        if (tid == 0) {
            g_bb[s] = r0[0];
            g_cb[s] = r1[0];
            gam_sh = -0.5f * r2[0];
        }
        __syncthreads();
        if (tid < MP) {
            float uval = 0.0f;
            if (tid < MM) {
                float wv = w[tid];
                uval = expf(gam_sh * wv * wv);
            }
            g_u[s * MP + tid] = uval;
        }
    }
}

// ---------- main ----------
__global__ void __launch_bounds__(THREADS, 1)
k_main(const float* __restrict__ z, const float* __restrict__ mu,
       const int* __restrict__ A, const int* __restrict__ B,
       const float* __restrict__ w, float* __restrict__ out_lp) {
    extern __shared__ float sm[];
    float* su    = sm;                        // NS*MP = 14144
    float* zs    = su + NS * MP;              // 64*132 = 8448
    float* msps  = zs + ROWS * ZSTRIDE;       // 2048 (mu for GEMM; psum after)
    float* sG    = msps + 2048;               // 64*17 = 1088
    float* sz2   = sG + ROWS * 17;            // 64
    float* zpart = sz2 + ROWS;                // 64*8 = 512
    float* sPf   = zpart + ROWS * 8;          // NS*4 = 544

    int tid = threadIdx.x;
    int b0 = blockIdx.x * ROWS;

    // async copy of u-table (overlaps staging + GEMM)
    {
        const float4* gu4 = (const float4*)g_u;
        for (int i = tid; i < NS * MP / 4; i += THREADS) {
            unsigned int dst = (unsigned int)__cvta_generic_to_shared(su + 4 * i);
            asm volatile("cp.async.cg.shared.global [%0], [%1], 16;"
                         :: "r"(dst), "l"(gu4 + i));
        }
        asm volatile("cp.async.commit_group;");
    }

    // stage z tile + per-row partial sq-sums (8 threads per row)
    {
        int rrow = tid >> 3;                 // 0..63
        int c8   = tid & 7;
        const float4* zrow = (const float4*)(z + (size_t)(b0 + rrow) * DLAT);
        float* zd = zs + rrow * ZSTRIDE;
        float zz = 0.0f;
#pragma unroll
        for (int jj = 0; jj < 4; jj++) {
            int c4 = c8 + 8 * jj;
            float4 v = zrow[c4];
            float* dst = zd + c4 * 4;
            dst[0] = v.x; dst[1] = v.y; dst[2] = v.z; dst[3] = v.w;
            zz = fmaf(v.x, v.x, zz);
            zz = fmaf(v.y, v.y, zz);
            zz = fmaf(v.z, v.z, zz);
            zz = fmaf(v.w, v.w, zz);
        }
        zpart[rrow * 8 + c8] = zz;
    }
    for (int i = tid; i < DLAT * NK; i += THREADS) msps[i] = mu[i];
    if (tid < NS) {
        sPf[4 * tid + 0] = g_logpi[tid] - 0.5f * g_bb[tid];
        sPf[4 * tid + 1] = g_cb[tid];
        sPf[4 * tid + 2] = __int_as_float(A[tid]);
        sPf[4 * tid + 3] = __int_as_float(B[tid]);
    }
    __syncthreads();

    // z2 finalize
    if (tid < ROWS) {
        const float* zp = zpart + tid * 8;
        float t0 = zp[0] + zp[1], t1 = zp[2] + zp[3];
        float t2 = zp[4] + zp[5], t3 = zp[6] + zp[7];
        sz2[tid] = (t0 + t1) + (t2 + t3);
    }

    // fused GEMM: thread owns k and rows rb, rb+32 (ms loads amortized)
    {
        int k = tid & 15, rb = tid >> 4;     // rb in 0..31
        const float* zra = zs + rb * ZSTRIDE;
        const float* zrb = zs + (rb + 32) * ZSTRIDE;
        float acca = 0.0f, accb = 0.0f;
#pragma unroll 8
        for (int d4 = 0; d4 < DLAT / 4; d4++) {
            float4 va = *(const float4*)(zra + 4 * d4);
            float4 vb = *(const float4*)(zrb + 4 * d4);
            int db = d4 * 4;
            float m0 = msps[(db + 0) * NK + k];
            float m1 = msps[(db + 1) * NK + k];
            float m2 = msps[(db + 2) * NK + k];
            float m3 = msps[(db + 3) * NK + k];
            acca = fmaf(va.x, m0, acca);
            acca = fmaf(va.y, m1, acca);
            acca = fmaf(va.z, m2, acca);
            acca = fmaf(va.w, m3, acca);
            accb = fmaf(vb.x, m0, accb);
            accb = fmaf(vb.y, m1, accb);
            accb = fmaf(vb.z, m2, accb);
            accb = fmaf(vb.w, m3, accb);
        }
        sG[rb * 17 + k] = acca;
        sG[(rb + 32) * 17 + k] = accb;
    }
    asm volatile("cp.async.wait_group 0;");
    __syncthreads();   // fences GEMM results, u-table, msps->psum reuse

    // main loop: half-warp = state slot; lane owns 4 rows (r0i + 16*q)
    int lane = tid & 31;
    int warp = tid >> 5;                     // 0..15
    int r0i = lane & 15;
    int slot = warp * 2 + (lane >> 4);       // 0..31
    int cnt = (slot < 8) ? 5 : 4;            // 8*5 + 24*4 = 136
    float w1 = w[1];
    const float* gra = sG + r0i * 17;
    const float* grb = sG + (r0i + 16) * 17;
    const float* grc = sG + (r0i + 32) * 17;
    const float* grd = sG + (r0i + 48) * 17;
    const float4* sP4 = (const float4*)sPf;
    float acc_a = 0.0f, acc_b = 0.0f, acc_c = 0.0f, acc_d = 0.0f;

    int s = slot;
    // head prefetch for first state
    float4 P = sP4[s];
    int ia = __float_as_int(P.z), ib = __float_as_int(P.w);
    float gAa = gra[ia], gBa = gra[ib];
    float gAb = grb[ia], gBb = grb[ib];
    float gAc = grc[ia], gBc = grc[ib];
    float gAd = grd[ia], gBd = grd[ib];

#pragma unroll 1
    for (int i = 0; i < cnt; i++) {
        float r1a = __expf((gAa - gBa - P.y) * w1);
        float r1b = __expf((gAb - gBb - P.y) * w1);
        float r1c = __expf((gAc - gBc - P.y) * w1);
        float r1d = __expf((gAd - gBd - P.y) * w1);
        float ea = __expf(P.x + gBa);
        float eb = __expf(P.x + gBb);
        float ec = __expf(P.x + gBc);
        float ed = __expf(P.x + gBd);
        float r4a = (r1a * r1a) * (r1a * r1a);
        float r4b = (r1b * r1b) * (r1b * r1b);
        float r4c = (r1c * r1c) * (r1c * r1c);
        float r4d = (r1d * r1d) * (r1d * r1d);
        ull r4ap, r4bp, r4cp, r4dp;
        PACK2(r4ap, r4a); PACK2(r4bp, r4b);
        PACK2(r4cp, r4c); PACK2(r4dp, r4d);
        const ulonglong2* up = (const ulonglong2*)(su + s * MP);

        // prefetch next state's params + G (uniform per half-warp)
        int sn = s + NSLOT;
        int sc = (sn < NS) ? sn : s;
        float4 Pn = sP4[sc];
        int ian = __float_as_int(Pn.z), ibn = __float_as_int(Pn.w);
        float gAan = gra[ian], gBan = gra[ibn];
        float gAbn = grb[ian], gBbn = grb[ibn];
        float gAcn = grc[ian], gBcn = grc[ibn];
        float gAdn = grd[ian], gBdn = grd[ibn];

        // 2-deep software-pipelined Horner: coefficient loaded 2 iters ahead
        ull Fa01 = 0ull, Fa23 = 0ull, Fb01 = 0ull, Fb23 = 0ull;
        ull Fc01 = 0ull, Fc23 = 0ull, Fd01 = 0ull, Fd23 = 0ull;
        ulonglong2 u0 = up[MP / 4 - 1];
        ulonglong2 u1 = up[MP / 4 - 2];
#pragma unroll
        for (int g = MP / 4 - 1; g >= 0; g--) {
            ulonglong2 un;
            if (g >= 2) un = up[g - 2];
            FMA2(Fa01, r4ap, Fa01, u0.x);
            FMA2(Fa23, r4ap, Fa23, u0.y);
            FMA2(Fb01, r4bp, Fb01, u0.x);
            FMA2(Fb23, r4bp, Fb23, u0.y);
            FMA2(Fc01, r4cp, Fc01, u0.x);
            FMA2(Fc23, r4cp, Fc23, u0.y);
            FMA2(Fd01, r4dp, Fd01, u0.x);
            FMA2(Fd23, r4dp, Fd23, u0.y);
            u0 = u1;
            if (g >= 2) u1 = un;
        }

        // epilogue: V = F01 + r2*F23 ; f = V.lo + r1*V.hi
        ull V; float X, Y; ull r2p;
        PACK2(r2p, r1a * r1a);
        FMA2(V, r2p, Fa23, Fa01); UNPACK2(X, Y, V);
        acc_a = fmaf(ea, fmaf(r1a, Y, X), acc_a);
        PACK2(r2p, r1b * r1b);
        FMA2(V, r2p, Fb23, Fb01); UNPACK2(X, Y, V);
        acc_b = fmaf(eb, fmaf(r1b, Y, X), acc_b);
        PACK2(r2p, r1c * r1c);
        FMA2(V, r2p, Fc23, Fc01); UNPACK2(X, Y, V);
        acc_c = fmaf(ec, fmaf(r1c, Y, X), acc_c);
        PACK2(r2p, r1d * r1d);
        FMA2(V, r2p, Fd23, Fd01); UNPACK2(X, Y, V);
        acc_d = fmaf(ed, fmaf(r1d, Y, X), acc_d);

        P = Pn; s = sn;
        gAa = gAan; gBa = gBan; gAb = gAbn; gBb = gBbn;
        gAc = gAcn; gBc = gBcn; gAd = gAdn; gBd = gBdn;
    }

    float* psum = msps;                      // reuse as [NSLOT][ROWS]
    psum[slot * ROWS + r0i]      = acc_a;
    psum[slot * ROWS + r0i + 16] = acc_b;
    psum[slot * ROWS + r0i + 32] = acc_c;
    psum[slot * ROWS + r0i + 48] = acc_d;
    __syncthreads();
    if (tid < ROWS) {
        float tot = 0.0f;
#pragma unroll
        for (int q = 0; q < NSLOT; q++) tot += psum[q * ROWS + tid];
        const float C = -0.5f * (float)DLAT * 1.8378770664093453f;  // -D/2 ln(2pi)
        out_lp[b0 + tid] = C - 0.5f * sz2[tid] - logf((float)MM) + logf(tot);
    }
}

// ---------- launcher ----------
extern "C" void kernel_launch(void* const* d_in, const int* in_sizes, int n_in,
                              void* d_out, int out_size) {
    const float* z  = (const float*)d_in[0];
    const float* mu = (const float*)d_in[1];
    const float* pi = (const float*)d_in[2];
    const float* w  = (const float*)d_in[3];
    const int*   A  = (const int*)d_in[4];
    const int*   B  = (const int*)d_in[5];
    float* out = (float*)d_out;

    float* out_pi = nullptr;
    float* out_mu = nullptr;
    float* out_lp = out;
    if (out_size >= NS + DLAT * NK + NB) {
        out_pi = out;
        out_mu = out + NS;
        out_lp = out + NS + DLAT * NK;
    }

    const int SMEM = (NS * MP + ROWS * ZSTRIDE + 2048 + ROWS * 17 + ROWS
                      + ROWS * 8 + NS * 4) * 4;
    cudaFuncSetAttribute(k_main, cudaFuncAttributeMaxDynamicSharedMemorySize, SMEM);

    k_prep<<<1 + NS, 256>>>(pi, mu, A, B, w, out_pi, out_mu);
    k_main<<<NB / ROWS, THREADS, SMEM>>>(z, mu, A, B, w, out_lp);
}